// round 2
// baseline (speedup 1.0000x reference)
#include <cuda_runtime.h>

#define NB 8
#define PP 2048
#define DD 64
#define EPSI 1e-3f
#define INV_EPS 1000.0f
#define THRESH 0.1f
#define NPb (NB*PP)

__device__ __align__(256) float g_C[(size_t)NB * PP * PP]; // 134 MB cost matrix
__device__ __align__(256) float g_An[NPb * DD];
__device__ __align__(256) float g_Bn[NPb * DD];
__device__ __align__(256) float g_rs[NPb];
__device__ __align__(256) float g_cs[NPb];
__device__ __align__(256) float g_lmu[NPb];
__device__ __align__(256) float g_lnu[NPb];
__device__ __align__(256) float g_u[NPb];
__device__ __align__(256) float g_v[NPb];
__device__ __align__(256) float g_du[NPb];
__device__ int g_flag;

// ---------------- block reductions (256 threads, red[] >= 33 floats) -------
__device__ __forceinline__ float block_max256(float v, float* red) {
    __syncthreads();
    #pragma unroll
    for (int off = 16; off; off >>= 1) v = fmaxf(v, __shfl_xor_sync(0xffffffffu, v, off));
    int w = threadIdx.x >> 5, l = threadIdx.x & 31;
    if (l == 0) red[w] = v;
    __syncthreads();
    if (threadIdx.x < 32) {
        float x = (l < 8) ? red[l] : -3.0e38f;
        #pragma unroll
        for (int off = 4; off; off >>= 1) x = fmaxf(x, __shfl_xor_sync(0xffffffffu, x, off));
        if (l == 0) red[32] = x;
    }
    __syncthreads();
    return red[32];
}

__device__ __forceinline__ float block_sum256(float v, float* red) {
    __syncthreads();
    #pragma unroll
    for (int off = 16; off; off >>= 1) v += __shfl_xor_sync(0xffffffffu, v, off);
    int w = threadIdx.x >> 5, l = threadIdx.x & 31;
    if (l == 0) red[w] = v;
    __syncthreads();
    if (threadIdx.x < 32) {
        float x = (l < 8) ? red[l] : 0.0f;
        #pragma unroll
        for (int off = 4; off; off >>= 1) x += __shfl_xor_sync(0xffffffffu, x, off);
        if (l == 0) red[32] = x;
    }
    __syncthreads();
    return red[32];
}

// ---------------- prep: normalize inputs, zero state -----------------------
__global__ __launch_bounds__(256) void k_prep(const float* __restrict__ a,
                                              const float* __restrict__ b,
                                              float* __restrict__ out) {
    int idx = blockIdx.x * 256 + threadIdx.x;          // 0..16383
    {
        const float4* s = (const float4*)(a + (size_t)idx * DD);
        float nrm = 0.0f;
        #pragma unroll
        for (int q = 0; q < 16; q++) {
            float4 t = s[q];
            nrm += t.x * t.x + t.y * t.y + t.z * t.z + t.w * t.w;
        }
        float sc = 1.0f / fmaxf(sqrtf(nrm), 1e-12f);
        float4* d = (float4*)(g_An + (size_t)idx * DD);
        #pragma unroll
        for (int q = 0; q < 16; q++) {
            float4 t = s[q];
            t.x *= sc; t.y *= sc; t.z *= sc; t.w *= sc;
            d[q] = t;
        }
    }
    {
        const float4* s = (const float4*)(b + (size_t)idx * DD);
        float nrm = 0.0f;
        #pragma unroll
        for (int q = 0; q < 16; q++) {
            float4 t = s[q];
            nrm += t.x * t.x + t.y * t.y + t.z * t.z + t.w * t.w;
        }
        float sc = 1.0f / fmaxf(sqrtf(nrm), 1e-12f);
        float4* d = (float4*)(g_Bn + (size_t)idx * DD);
        #pragma unroll
        for (int q = 0; q < 16; q++) {
            float4 t = s[q];
            t.x *= sc; t.y *= sc; t.z *= sc; t.w *= sc;
            d[q] = t;
        }
    }
    g_u[idx] = 0.0f; g_v[idx] = 0.0f; g_rs[idx] = 0.0f; g_cs[idx] = 0.0f;
    if (idx < NB) out[idx] = 0.0f;
    if (idx == 0) g_flag = 0;
}

// ---------------- GEMM: C = 1 - Ahat . Bhat^T, fused S row/col sums --------
__global__ __launch_bounds__(256) void k_gemm() {
    __shared__ float As[128][33];
    __shared__ float Bs[32][132];
    int b = blockIdx.z;
    int row0 = blockIdx.y * 128, col0 = blockIdx.x * 128;
    const float* Ab = g_An + (size_t)b * PP * DD;
    const float* Bb = g_Bn + (size_t)b * PP * DD;
    int t = threadIdx.x, tx = t & 15, ty = t >> 4;

    unsigned long long acc[8][4];
    #pragma unroll
    for (int i = 0; i < 8; i++)
        #pragma unroll
        for (int j = 0; j < 4; j++) acc[i][j] = 0ULL;

    #pragma unroll
    for (int kp = 0; kp < 2; kp++) {
        __syncthreads();
        int kq = t & 7, rq = t >> 3;
        #pragma unroll
        for (int p = 0; p < 4; p++) {
            int r = p * 32 + rq;
            float4 v = *(const float4*)(Ab + (size_t)(row0 + r) * DD + kp * 32 + kq * 4);
            As[r][kq * 4 + 0] = v.x; As[r][kq * 4 + 1] = v.y;
            As[r][kq * 4 + 2] = v.z; As[r][kq * 4 + 3] = v.w;
            float4 w = *(const float4*)(Bb + (size_t)(col0 + r) * DD + kp * 32 + kq * 4);
            Bs[kq * 4 + 0][r] = w.x; Bs[kq * 4 + 1][r] = w.y;
            Bs[kq * 4 + 2][r] = w.z; Bs[kq * 4 + 3][r] = w.w;
        }
        __syncthreads();
        #pragma unroll 4
        for (int k = 0; k < 32; k++) {
            union { float4 f; unsigned long long u[2]; } b0, b1;
            b0.f = *(const float4*)&Bs[k][tx * 4];
            b1.f = *(const float4*)&Bs[k][64 + tx * 4];
            #pragma unroll
            for (int i = 0; i < 8; i++) {
                unsigned int ai = __float_as_uint(As[ty * 8 + i][k]);
                unsigned long long a2;
                asm("mov.b64 %0, {%1, %1};" : "=l"(a2) : "r"(ai));
                asm("fma.rn.f32x2 %0, %1, %2, %0;" : "+l"(acc[i][0]) : "l"(a2), "l"(b0.u[0]));
                asm("fma.rn.f32x2 %0, %1, %2, %0;" : "+l"(acc[i][1]) : "l"(a2), "l"(b0.u[1]));
                asm("fma.rn.f32x2 %0, %1, %2, %0;" : "+l"(acc[i][2]) : "l"(a2), "l"(b1.u[0]));
                asm("fma.rn.f32x2 %0, %1, %2, %0;" : "+l"(acc[i][3]) : "l"(a2), "l"(b1.u[1]));
            }
        }
    }
    __syncthreads();

    // epilogue: write C, gather S-sums (S = dot)
    float rs[8], cs8[8];
    #pragma unroll
    for (int j = 0; j < 8; j++) cs8[j] = 0.0f;
    #pragma unroll
    for (int i = 0; i < 8; i++) {
        float vals[8];  // S values; cols: 0..3 -> tx*4+j ; 4..7 -> 64+tx*4+(j-4)
        #pragma unroll
        for (int jp = 0; jp < 4; jp++) {
            union { unsigned long long u; float2 f; } cv; cv.u = acc[i][jp];
            vals[jp * 2 + 0] = cv.f.x;
            vals[jp * 2 + 1] = cv.f.y;
        }
        // reorder: acc[i][0] = cols tx*4+0,1 ; [1] = +2,3 ; [2] = 64+tx*4+0,1 ; [3] = +2,3
        size_t base = ((size_t)b * PP + row0 + ty * 8 + i) * (size_t)PP + col0;
        *(float4*)(g_C + base + tx * 4) =
            make_float4(1.0f - vals[0], 1.0f - vals[1], 1.0f - vals[2], 1.0f - vals[3]);
        *(float4*)(g_C + base + 64 + tx * 4) =
            make_float4(1.0f - vals[4], 1.0f - vals[5], 1.0f - vals[6], 1.0f - vals[7]);
        float rsum = 0.0f;
        #pragma unroll
        for (int j = 0; j < 8; j++) { rsum += vals[j]; cs8[j] += vals[j]; }
        rs[i] = rsum;
    }
    float* red = (float*)As;   // 2048 floats needed, As has 4224
    #pragma unroll
    for (int i = 0; i < 8; i++) red[(ty * 8 + i) * 16 + tx] = rs[i];
    __syncthreads();
    if (t < 128) {
        float s = 0.0f;
        #pragma unroll
        for (int q = 0; q < 16; q++) s += red[t * 16 + q];
        atomicAdd(&g_rs[b * PP + row0 + t], s);
    }
    __syncthreads();
    #pragma unroll
    for (int j = 0; j < 8; j++) {
        int cc = (j < 4) ? (tx * 4 + j) : (64 + tx * 4 + (j - 4));
        red[cc * 16 + ty] = cs8[j];
    }
    __syncthreads();
    if (t < 128) {
        float s = 0.0f;
        #pragma unroll
        for (int q = 0; q < 16; q++) s += red[t * 16 + q];
        atomicAdd(&g_cs[b * PP + col0 + t], s);
    }
}

// ---------------- weights -> log(mu+1e-8) ----------------------------------
__device__ __forceinline__ void wproc(const float* __restrict__ sum,
                                      float* __restrict__ out, float* red, int t) {
    float raw[8], s = 0.0f;
    #pragma unroll
    for (int q = 0; q < 8; q++) {
        raw[q] = sum[t + 256 * q] * (1.0f / PP);
        s += fabsf(raw[q]);
    }
    s = block_sum256(s, red);
    float inv1 = 1.0f / fmaxf(s, 1e-12f);
    float c[8]; float s2 = 0.0f;
    #pragma unroll
    for (int q = 0; q < 8; q++) { c[q] = fmaxf(raw[q] * inv1, 0.0f); s2 += fabsf(c[q]); }
    s2 = block_sum256(s2, red);
    float inv2 = 1.0f / fmaxf(s2, 1e-12f);
    #pragma unroll
    for (int q = 0; q < 8; q++) out[t + 256 * q] = logf(c[q] * inv2 + 1e-8f);
}

__global__ __launch_bounds__(256) void k_weights() {
    __shared__ float red[40];
    int b = blockIdx.x, t = threadIdx.x;
    wproc(g_rs + b * PP, g_lmu + b * PP, red, t);
    wproc(g_cs + b * PP, g_lnu + b * PP, red, t);
}

// ---------------- row pass: u_i = eps*(lmu_i - lse_j((v_j - C_ij)/eps)) ----
__global__ __launch_bounds__(256) void k_row() {
    if (g_flag) return;
    __shared__ float red[40];
    int bi = blockIdx.x;                 // b*PP + i
    int b = bi >> 11;
    const float* Crow = g_C + ((size_t)bi << 11);
    const float* vv = g_v + (b << 11);
    int t = threadIdx.x;
    float4 c0 = *(const float4*)(Crow + t * 4);
    float4 c1 = *(const float4*)(Crow + 1024 + t * 4);
    float4 v0 = *(const float4*)(vv + t * 4);
    float4 v1 = *(const float4*)(vv + 1024 + t * 4);
    float x[8];
    x[0] = (v0.x - c0.x) * INV_EPS; x[1] = (v0.y - c0.y) * INV_EPS;
    x[2] = (v0.z - c0.z) * INV_EPS; x[3] = (v0.w - c0.w) * INV_EPS;
    x[4] = (v1.x - c1.x) * INV_EPS; x[5] = (v1.y - c1.y) * INV_EPS;
    x[6] = (v1.z - c1.z) * INV_EPS; x[7] = (v1.w - c1.w) * INV_EPS;
    float m = x[0];
    #pragma unroll
    for (int q = 1; q < 8; q++) m = fmaxf(m, x[q]);
    m = block_max256(m, red);
    float s = 0.0f;
    #pragma unroll
    for (int q = 0; q < 8; q++) s += __expf(x[q] - m);
    s = block_sum256(s, red);
    if (t == 0) {
        float lse = m + __logf(s);
        float un = EPSI * (g_lmu[bi] - lse);
        g_du[bi] = fabsf(un - g_u[bi]);
        g_u[bi] = un;
    }
}

// ---------------- col pass: v_j = eps*(lnu_j - lse_i((u_i - C_ij)/eps)) ----
__global__ __launch_bounds__(256) void k_col() {
    if (g_flag) return;
    __shared__ float sm_m[16][17], sm_s[16][17];
    int blk = blockIdx.x;                // 1024 = 8 batches * 128 col-tiles
    int b = blk >> 7;
    int j0 = (blk & 127) * 16;
    int t = threadIdx.x, c = t & 15, g = t >> 4;   // 16 cols x 16 row-groups
    const float* Cb = g_C + ((size_t)b << 22);
    const float* ub = g_u + (b << 11);
    float m = -3.0e38f, s = 0.0f;
    int r0 = g * 128;
    for (int r = r0; r < r0 + 128; r += 8) {
        float4 ua = *(const float4*)(ub + r);
        float4 uc = *(const float4*)(ub + r + 4);
        float xv[8];
        xv[0] = (ua.x - Cb[((size_t)(r + 0) << 11) + j0 + c]) * INV_EPS;
        xv[1] = (ua.y - Cb[((size_t)(r + 1) << 11) + j0 + c]) * INV_EPS;
        xv[2] = (ua.z - Cb[((size_t)(r + 2) << 11) + j0 + c]) * INV_EPS;
        xv[3] = (ua.w - Cb[((size_t)(r + 3) << 11) + j0 + c]) * INV_EPS;
        xv[4] = (uc.x - Cb[((size_t)(r + 4) << 11) + j0 + c]) * INV_EPS;
        xv[5] = (uc.y - Cb[((size_t)(r + 5) << 11) + j0 + c]) * INV_EPS;
        xv[6] = (uc.z - Cb[((size_t)(r + 6) << 11) + j0 + c]) * INV_EPS;
        xv[7] = (uc.w - Cb[((size_t)(r + 7) << 11) + j0 + c]) * INV_EPS;
        float lm = xv[0];
        #pragma unroll
        for (int q = 1; q < 8; q++) lm = fmaxf(lm, xv[q]);
        float mn = fmaxf(m, lm);
        s *= __expf(m - mn);
        #pragma unroll
        for (int q = 0; q < 8; q++) s += __expf(xv[q] - mn);
        m = mn;
    }
    sm_m[g][c] = m; sm_s[g][c] = s;
    __syncthreads();
    if (t < 16) {
        float M = sm_m[0][t];
        #pragma unroll
        for (int gg = 1; gg < 16; gg++) M = fmaxf(M, sm_m[gg][t]);
        float S = 0.0f;
        #pragma unroll
        for (int gg = 0; gg < 16; gg++) S += sm_s[gg][t] * __expf(sm_m[gg][t] - M);
        float lse = M + __logf(S);
        int j = b * PP + j0 + t;
        g_v[j] = EPSI * (g_lnu[j] - lse);
    }
}

// ---------------- err check: flag = (mean_b sum_i |du|) < THRESH -----------
__global__ __launch_bounds__(256) void k_err() {
    if (g_flag) return;
    __shared__ float red[40];
    int t = threadIdx.x;
    float s = 0.0f;
    for (int q = t; q < NPb / 4; q += 256) {
        float4 d = ((const float4*)g_du)[q];
        s += d.x + d.y + d.z + d.w;
    }
    s = block_sum256(s, red);
    if (t == 0 && (s * (1.0f / NB)) < THRESH) g_flag = 1;
}

// ---------------- final: out[b] = sum_ij exp((u+v-C)/eps) * C --------------
__global__ __launch_bounds__(256) void k_final(float* __restrict__ out) {
    __shared__ float red[40];
    int bi = blockIdx.x;
    int b = bi >> 11;
    const float* Crow = g_C + ((size_t)bi << 11);
    const float* vv = g_v + (b << 11);
    float ui = g_u[bi];
    int t = threadIdx.x;
    float4 c0 = *(const float4*)(Crow + t * 4);
    float4 c1 = *(const float4*)(Crow + 1024 + t * 4);
    float4 v0 = *(const float4*)(vv + t * 4);
    float4 v1 = *(const float4*)(vv + 1024 + t * 4);
    float s = 0.0f;
    s += __expf((ui + v0.x - c0.x) * INV_EPS) * c0.x;
    s += __expf((ui + v0.y - c0.y) * INV_EPS) * c0.y;
    s += __expf((ui + v0.z - c0.z) * INV_EPS) * c0.z;
    s += __expf((ui + v0.w - c0.w) * INV_EPS) * c0.w;
    s += __expf((ui + v1.x - c1.x) * INV_EPS) * c1.x;
    s += __expf((ui + v1.y - c1.y) * INV_EPS) * c1.y;
    s += __expf((ui + v1.z - c1.z) * INV_EPS) * c1.z;
    s += __expf((ui + v1.w - c1.w) * INV_EPS) * c1.w;
    s = block_sum256(s, red);
    if (t == 0) atomicAdd(&out[b], s);
}

extern "C" void kernel_launch(void* const* d_in, const int* in_sizes, int n_in,
                              void* d_out, int out_size) {
    const float* a = (const float*)d_in[0];
    const float* b = (const float*)d_in[1];
    float* out = (float*)d_out;
    k_prep<<<64, 256>>>(a, b, out);
    dim3 gg(16, 16, NB);
    k_gemm<<<gg, 256>>>();
    k_weights<<<NB, 256>>>();
    for (int it = 0; it < 10; it++) {
        k_row<<<NB * PP, 256>>>();
        k_col<<<1024, 256>>>();
        k_err<<<1, 256>>>();
    }
    k_final<<<NB * PP, 256>>>(out);
}

// round 3
// speedup vs baseline: 1.2268x; 1.2268x over previous
#include <cuda_runtime.h>

#define NB 8
#define PP 2048
#define DD 64
#define EPSI 1e-3f
#define INV_EPS 1000.0f
#define NPb (NB*PP)

__device__ __align__(256) float g_C[(size_t)NB * PP * PP]; // 134 MB cost matrix
__device__ __align__(256) float g_An[NPb * DD];
__device__ __align__(256) float g_Bn[NPb * DD];
__device__ __align__(256) float g_rs[NPb];
__device__ __align__(256) float g_cs[NPb];
__device__ __align__(256) float g_lmu[NPb];
__device__ __align__(256) float g_lnu[NPb];
__device__ __align__(256) float g_u[NPb];
__device__ __align__(256) float g_v[NPb];
__device__ __align__(256) float g_pm[NB * 8 * PP];   // col-pass partial max
__device__ __align__(256) float g_ps[NB * 8 * PP];   // col-pass partial sum
__device__ float g_errsum[16];
__device__ int g_flag;

// ---------------- block sum reduction (256 threads) ------------------------
__device__ __forceinline__ float block_sum256(float v, float* red) {
    __syncthreads();
    #pragma unroll
    for (int off = 16; off; off >>= 1) v += __shfl_xor_sync(0xffffffffu, v, off);
    int w = threadIdx.x >> 5, l = threadIdx.x & 31;
    if (l == 0) red[w] = v;
    __syncthreads();
    if (threadIdx.x < 32) {
        float x = (l < 8) ? red[l] : 0.0f;
        #pragma unroll
        for (int off = 4; off; off >>= 1) x += __shfl_xor_sync(0xffffffffu, x, off);
        if (l == 0) red[32] = x;
    }
    __syncthreads();
    return red[32];
}

// ---------------- prep: normalize inputs, zero state -----------------------
__global__ __launch_bounds__(256) void k_prep(const float* __restrict__ a,
                                              const float* __restrict__ b,
                                              float* __restrict__ out) {
    int idx = blockIdx.x * 256 + threadIdx.x;          // 0..16383
    {
        const float4* s = (const float4*)(a + (size_t)idx * DD);
        float nrm = 0.0f;
        #pragma unroll
        for (int q = 0; q < 16; q++) {
            float4 t = s[q];
            nrm += t.x * t.x + t.y * t.y + t.z * t.z + t.w * t.w;
        }
        float sc = 1.0f / fmaxf(sqrtf(nrm), 1e-12f);
        float4* d = (float4*)(g_An + (size_t)idx * DD);
        #pragma unroll
        for (int q = 0; q < 16; q++) {
            float4 t = s[q];
            t.x *= sc; t.y *= sc; t.z *= sc; t.w *= sc;
            d[q] = t;
        }
    }
    {
        const float4* s = (const float4*)(b + (size_t)idx * DD);
        float nrm = 0.0f;
        #pragma unroll
        for (int q = 0; q < 16; q++) {
            float4 t = s[q];
            nrm += t.x * t.x + t.y * t.y + t.z * t.z + t.w * t.w;
        }
        float sc = 1.0f / fmaxf(sqrtf(nrm), 1e-12f);
        float4* d = (float4*)(g_Bn + (size_t)idx * DD);
        #pragma unroll
        for (int q = 0; q < 16; q++) {
            float4 t = s[q];
            t.x *= sc; t.y *= sc; t.z *= sc; t.w *= sc;
            d[q] = t;
        }
    }
    g_u[idx] = 0.0f; g_v[idx] = 0.0f; g_rs[idx] = 0.0f; g_cs[idx] = 0.0f;
    if (idx < NB) out[idx] = 0.0f;
    if (idx < 16) g_errsum[idx] = 0.0f;
    if (idx == 0) g_flag = 0;
}

// ---------------- GEMM: C = 1 - Ahat . Bhat^T, fused S row/col sums --------
__global__ __launch_bounds__(256) void k_gemm() {
    __shared__ float As[128][33];
    __shared__ float Bs[32][132];
    int b = blockIdx.z;
    int row0 = blockIdx.y * 128, col0 = blockIdx.x * 128;
    const float* Ab = g_An + (size_t)b * PP * DD;
    const float* Bb = g_Bn + (size_t)b * PP * DD;
    int t = threadIdx.x, tx = t & 15, ty = t >> 4;

    unsigned long long acc[8][4];
    #pragma unroll
    for (int i = 0; i < 8; i++)
        #pragma unroll
        for (int j = 0; j < 4; j++) acc[i][j] = 0ULL;

    #pragma unroll
    for (int kp = 0; kp < 2; kp++) {
        __syncthreads();
        int kq = t & 7, rq = t >> 3;
        #pragma unroll
        for (int p = 0; p < 4; p++) {
            int r = p * 32 + rq;
            float4 v = *(const float4*)(Ab + (size_t)(row0 + r) * DD + kp * 32 + kq * 4);
            As[r][kq * 4 + 0] = v.x; As[r][kq * 4 + 1] = v.y;
            As[r][kq * 4 + 2] = v.z; As[r][kq * 4 + 3] = v.w;
            float4 w = *(const float4*)(Bb + (size_t)(col0 + r) * DD + kp * 32 + kq * 4);
            Bs[kq * 4 + 0][r] = w.x; Bs[kq * 4 + 1][r] = w.y;
            Bs[kq * 4 + 2][r] = w.z; Bs[kq * 4 + 3][r] = w.w;
        }
        __syncthreads();
        #pragma unroll 4
        for (int k = 0; k < 32; k++) {
            union { float4 f; unsigned long long u[2]; } b0, b1;
            b0.f = *(const float4*)&Bs[k][tx * 4];
            b1.f = *(const float4*)&Bs[k][64 + tx * 4];
            #pragma unroll
            for (int i = 0; i < 8; i++) {
                unsigned int ai = __float_as_uint(As[ty * 8 + i][k]);
                unsigned long long a2;
                asm("mov.b64 %0, {%1, %1};" : "=l"(a2) : "r"(ai));
                asm("fma.rn.f32x2 %0, %1, %2, %0;" : "+l"(acc[i][0]) : "l"(a2), "l"(b0.u[0]));
                asm("fma.rn.f32x2 %0, %1, %2, %0;" : "+l"(acc[i][1]) : "l"(a2), "l"(b0.u[1]));
                asm("fma.rn.f32x2 %0, %1, %2, %0;" : "+l"(acc[i][2]) : "l"(a2), "l"(b1.u[0]));
                asm("fma.rn.f32x2 %0, %1, %2, %0;" : "+l"(acc[i][3]) : "l"(a2), "l"(b1.u[1]));
            }
        }
    }
    __syncthreads();

    float rs[8], cs8[8];
    #pragma unroll
    for (int j = 0; j < 8; j++) cs8[j] = 0.0f;
    #pragma unroll
    for (int i = 0; i < 8; i++) {
        float vals[8];
        #pragma unroll
        for (int jp = 0; jp < 4; jp++) {
            union { unsigned long long u; float2 f; } cv; cv.u = acc[i][jp];
            vals[jp * 2 + 0] = cv.f.x;
            vals[jp * 2 + 1] = cv.f.y;
        }
        size_t base = ((size_t)b * PP + row0 + ty * 8 + i) * (size_t)PP + col0;
        *(float4*)(g_C + base + tx * 4) =
            make_float4(1.0f - vals[0], 1.0f - vals[1], 1.0f - vals[2], 1.0f - vals[3]);
        *(float4*)(g_C + base + 64 + tx * 4) =
            make_float4(1.0f - vals[4], 1.0f - vals[5], 1.0f - vals[6], 1.0f - vals[7]);
        float rsum = 0.0f;
        #pragma unroll
        for (int j = 0; j < 8; j++) { rsum += vals[j]; cs8[j] += vals[j]; }
        rs[i] = rsum;
    }
    float* red = (float*)As;
    #pragma unroll
    for (int i = 0; i < 8; i++) red[(ty * 8 + i) * 16 + tx] = rs[i];
    __syncthreads();
    if (t < 128) {
        float s = 0.0f;
        #pragma unroll
        for (int q = 0; q < 16; q++) s += red[t * 16 + q];
        atomicAdd(&g_rs[b * PP + row0 + t], s);
    }
    __syncthreads();
    #pragma unroll
    for (int j = 0; j < 8; j++) {
        int cc = (j < 4) ? (tx * 4 + j) : (64 + tx * 4 + (j - 4));
        red[cc * 16 + ty] = cs8[j];
    }
    __syncthreads();
    if (t < 128) {
        float s = 0.0f;
        #pragma unroll
        for (int q = 0; q < 16; q++) s += red[t * 16 + q];
        atomicAdd(&g_cs[b * PP + col0 + t], s);
    }
}

// ---------------- weights -> log(mu+1e-8) ----------------------------------
__device__ __forceinline__ void wproc(const float* __restrict__ sum,
                                      float* __restrict__ out, float* red, int t) {
    float raw[8], s = 0.0f;
    #pragma unroll
    for (int q = 0; q < 8; q++) {
        raw[q] = sum[t + 256 * q] * (1.0f / PP);
        s += fabsf(raw[q]);
    }
    s = block_sum256(s, red);
    float inv1 = 1.0f / fmaxf(s, 1e-12f);
    float c[8]; float s2 = 0.0f;
    #pragma unroll
    for (int q = 0; q < 8; q++) { c[q] = fmaxf(raw[q] * inv1, 0.0f); s2 += fabsf(c[q]); }
    s2 = block_sum256(s2, red);
    float inv2 = 1.0f / fmaxf(s2, 1e-12f);
    #pragma unroll
    for (int q = 0; q < 8; q++) out[t + 256 * q] = logf(c[q] * inv2 + 1e-8f);
}

__global__ __launch_bounds__(256) void k_weights() {
    __shared__ float red[40];
    int b = blockIdx.x, t = threadIdx.x;
    wproc(g_rs + b * PP, g_lmu + b * PP, red, t);
    wproc(g_cs + b * PP, g_lnu + b * PP, red, t);
}

// ---------- row pass (warp-per-row): u_i = eps*(lmu_i - lse_j((v_j-C_ij)/eps))
__global__ __launch_bounds__(256) void k_row(int it) {
    if (g_flag) return;
    __shared__ float vs[2048];
    __shared__ float erw[8];
    int b = blockIdx.x >> 8;
    int t = threadIdx.x, l = t & 31, w = t >> 5;
    // stage v[b] into smem
    ((float4*)vs)[t] = ((const float4*)(g_v + (b << 11)))[t];
    ((float4*)vs)[t + 256] = ((const float4*)(g_v + (b << 11)))[t + 256];
    __syncthreads();

    int bi = (b << 11) + (blockIdx.x & 255) * 8 + w;
    const float* Crow = g_C + ((size_t)bi << 11);
    float m = -3.0e38f, s = 0.0f;
    #pragma unroll
    for (int p = 0; p < 2; p++) {
        float4 c4[8];
        #pragma unroll
        for (int k = 0; k < 8; k++)
            c4[k] = *(const float4*)(Crow + p * 1024 + k * 128 + l * 4);
        float lm = -3.0e38f;
        #pragma unroll
        for (int k = 0; k < 8; k++) {
            float4 v4 = *(const float4*)(vs + p * 1024 + k * 128 + l * 4);
            c4[k].x = (v4.x - c4[k].x) * INV_EPS;
            c4[k].y = (v4.y - c4[k].y) * INV_EPS;
            c4[k].z = (v4.z - c4[k].z) * INV_EPS;
            c4[k].w = (v4.w - c4[k].w) * INV_EPS;
            lm = fmaxf(lm, fmaxf(fmaxf(c4[k].x, c4[k].y), fmaxf(c4[k].z, c4[k].w)));
        }
        float mn = fmaxf(m, lm);
        s *= __expf(m - mn);
        #pragma unroll
        for (int k = 0; k < 8; k++) {
            s += __expf(c4[k].x - mn); s += __expf(c4[k].y - mn);
            s += __expf(c4[k].z - mn); s += __expf(c4[k].w - mn);
        }
        m = mn;
    }
    // warp-level (m,s) merge
    #pragma unroll
    for (int off = 16; off; off >>= 1) {
        float om = __shfl_xor_sync(0xffffffffu, m, off);
        float os = __shfl_xor_sync(0xffffffffu, s, off);
        float mn = fmaxf(m, om);
        s = s * __expf(m - mn) + os * __expf(om - mn);
        m = mn;
    }
    if (l == 0) {
        float lse = m + __logf(s);
        float un = EPSI * (g_lmu[bi] - lse);
        erw[w] = fabsf(un - g_u[bi]);
        g_u[bi] = un;
    }
    __syncthreads();
    if (t == 0) {
        float e = 0.0f;
        #pragma unroll
        for (int q = 0; q < 8; q++) e += erw[q];
        atomicAdd(&g_errsum[it], e);
    }
}

// ---------- col pass partials: per (b, row-chunk of 256) online lse over rows
__global__ __launch_bounds__(256) void k_col() {
    if (g_flag) return;
    __shared__ float us[256];
    int blk = blockIdx.x;                  // 512 = 8 b * 8 tiles * 8 chunks
    int b = blk >> 6, tile = (blk >> 3) & 7, chunk = blk & 7;
    int t = threadIdx.x;
    int j = (tile << 8) + t;
    int r0 = chunk << 8;
    us[t] = g_u[(b << 11) + r0 + t];
    __syncthreads();
    const float* Cb = g_C + ((size_t)b << 22) + ((size_t)r0 << 11) + j;
    float m = -3.0e38f, s = 0.0f;
    for (int r = 0; r < 256; r += 16) {
        float c[16];
        #pragma unroll
        for (int q = 0; q < 16; q++) c[q] = Cb[(size_t)q << 11];
        Cb += (size_t)16 << 11;
        float lm = -3.0e38f;
        #pragma unroll
        for (int q = 0; q < 16; q++) {
            c[q] = (us[r + q] - c[q]) * INV_EPS;
            lm = fmaxf(lm, c[q]);
        }
        float mn = fmaxf(m, lm);
        s *= __expf(m - mn);
        #pragma unroll
        for (int q = 0; q < 16; q++) s += __expf(c[q] - mn);
        m = mn;
    }
    int pidx = ((b * 8 + chunk) << 11) + j;
    g_pm[pidx] = m;
    g_ps[pidx] = s;
}

// ---------- combine col partials -> v; set early-stop flag ------------------
__global__ __launch_bounds__(256) void k_combine(int it) {
    if (g_flag) return;
    int t = blockIdx.x * 256 + threadIdx.x;     // 16384 = b*2048 + j
    int b = t >> 11, j = t & 2047;
    float mv[8], sv[8];
    #pragma unroll
    for (int ch = 0; ch < 8; ch++) {
        mv[ch] = g_pm[((b * 8 + ch) << 11) + j];
        sv[ch] = g_ps[((b * 8 + ch) << 11) + j];
    }
    float M = mv[0];
    #pragma unroll
    for (int ch = 1; ch < 8; ch++) M = fmaxf(M, mv[ch]);
    float S = 0.0f;
    #pragma unroll
    for (int ch = 0; ch < 8; ch++) S += sv[ch] * __expf(mv[ch] - M);
    g_v[t] = EPSI * (g_lnu[t] - (M + __logf(S)));
    if (t == 0) {
        // err = sum(|du|)/NB < 0.1  <=>  sum < 0.8   (errsum complete: k_row retired)
        if (g_errsum[it] < 0.1f * NB) g_flag = 1;
    }
}

// ---------- final (warp-per-row): out[b] = sum_ij exp((u+v-C)/eps)*C --------
__global__ __launch_bounds__(256) void k_final(float* __restrict__ out) {
    __shared__ float vs[2048];
    __shared__ float srw[8];
    int b = blockIdx.x >> 8;
    int t = threadIdx.x, l = t & 31, w = t >> 5;
    ((float4*)vs)[t] = ((const float4*)(g_v + (b << 11)))[t];
    ((float4*)vs)[t + 256] = ((const float4*)(g_v + (b << 11)))[t + 256];
    __syncthreads();
    int bi = (b << 11) + (blockIdx.x & 255) * 8 + w;
    const float* Crow = g_C + ((size_t)bi << 11);
    float ui = g_u[bi];
    float s = 0.0f;
    #pragma unroll
    for (int p = 0; p < 2; p++) {
        float4 c4[8];
        #pragma unroll
        for (int k = 0; k < 8; k++)
            c4[k] = *(const float4*)(Crow + p * 1024 + k * 128 + l * 4);
        #pragma unroll
        for (int k = 0; k < 8; k++) {
            float4 v4 = *(const float4*)(vs + p * 1024 + k * 128 + l * 4);
            s += __expf((ui + v4.x - c4[k].x) * INV_EPS) * c4[k].x;
            s += __expf((ui + v4.y - c4[k].y) * INV_EPS) * c4[k].y;
            s += __expf((ui + v4.z - c4[k].z) * INV_EPS) * c4[k].z;
            s += __expf((ui + v4.w - c4[k].w) * INV_EPS) * c4[k].w;
        }
    }
    #pragma unroll
    for (int off = 16; off; off >>= 1) s += __shfl_xor_sync(0xffffffffu, s, off);
    if (l == 0) srw[w] = s;
    __syncthreads();
    if (t == 0) {
        float e = 0.0f;
        #pragma unroll
        for (int q = 0; q < 8; q++) e += srw[q];
        atomicAdd(&out[b], e);
    }
}

extern "C" void kernel_launch(void* const* d_in, const int* in_sizes, int n_in,
                              void* d_out, int out_size) {
    const float* a = (const float*)d_in[0];
    const float* b = (const float*)d_in[1];
    float* out = (float*)d_out;
    k_prep<<<64, 256>>>(a, b, out);
    dim3 gg(16, 16, NB);
    k_gemm<<<gg, 256>>>();
    k_weights<<<NB, 256>>>();
    for (int it = 0; it < 10; it++) {
        k_row<<<2048, 256>>>(it);
        k_col<<<512, 256>>>();
        k_combine<<<64, 256>>>(it);
    }
    k_final<<<2048, 256>>>(out);
}